// round 7
// baseline (speedup 1.0000x reference)
#include <cuda_runtime.h>
#include <cuda_bf16.h>
#include <cooperative_groups.h>

namespace cg = cooperative_groups;

// Problem constants (pinned by the reference)
#define B_DIM   64
#define S_DIM   8192
#define D_DIM   64
#define N_BINS  256                 // output bins; bin 256 = dummy (T >= 256)
#define NCHUNK  4                   // CTAs (cluster size) per batch in the sort
#define CHUNK_S (S_DIM / NCHUNK)    // 2048 tokens per chunk
#define NBIN1   (N_BINS + 1)        // 257 (incl. dummy)
#define STARTS_PER_B 258

// Scratch (allocation-free rule: __device__ globals)
__device__ int2 g_sorted[B_DIM * S_DIM];          // (x, w-bits), bin-contiguous per batch
__device__ int  g_start [B_DIM * STARTS_PER_B];   // per-batch exclusive bin starts

// ---------------------------------------------------------------------------
// K1: fused per-batch counting sort, ONE kernel.
// 64 clusters x 4 CTAs (one cluster per batch), 512 threads/CTA.
//   phase A: each CTA bins its 2048-token chunk -> smem bin cache + smem hist
//   cluster.sync (~380 cyc)
//   phase B: each CTA reads the 4 chunk histograms over DSMEM, Hillis-Steele
//            scans 257 entries in smem -> batch-wide bin bases + this chunk's
//            write cursor, then scatters packed (x, exp(embedW[x])) pairs
//            with PRIVATE smem offsets. No global hist/bins round-trip,
//            no second launch. Chunk-0 CTA publishes g_start for K2.
// ---------------------------------------------------------------------------
__global__ __launch_bounds__(512, 2) __cluster_dims__(NCHUNK, 1, 1)
void k_sort(const float* __restrict__ T, const int* __restrict__ X,
            const float* __restrict__ embedW)
{
    __shared__ int            hist[NBIN1];
    __shared__ int            scan[NBIN1];
    __shared__ int            offs[NBIN1];
    __shared__ unsigned short sbin[CHUNK_S];   // 4 KB bin cache

    cg::cluster_group cluster = cg::this_cluster();
    const int c   = (int)cluster.block_rank();     // chunk 0..3
    const int b   = blockIdx.x >> 2;               // batch = cluster id
    const int tid = threadIdx.x;

    for (int i = tid; i < NBIN1; i += 512) hist[i] = 0;
    __syncthreads();

    // --- phase A: bin + local histogram ---
    const float* Tb = T + b * S_DIM + c * CHUNK_S;
    #pragma unroll 4
    for (int s = tid; s < CHUNK_S; s += 512) {
        float t = Tb[s];
        int bin = (t < 256.0f) ? (int)t : N_BINS;  // t >= 0 -> (int)t == floor
        sbin[s] = (unsigned short)bin;
        atomicAdd(&hist[bin], 1);
    }
    cluster.sync();

    // --- phase B: gather peer histograms via DSMEM, scan, scatter ---
    int tot = 0, part = 0;
    if (tid < NBIN1) {
        #pragma unroll
        for (int cc = 0; cc < NCHUNK; ++cc) {
            const int* rh = cluster.map_shared_rank(hist, cc);
            int h = rh[tid];
            tot += h;
            if (cc < c) part += h;
        }
        scan[tid] = tot;
    }
    __syncthreads();

    // Hillis-Steele inclusive scan over 257 entries
    for (int d = 1; d < NBIN1; d <<= 1) {
        int v = 0;
        if (tid < NBIN1 && tid >= d) v = scan[tid - d];
        __syncthreads();
        if (tid < NBIN1) scan[tid] += v;
        __syncthreads();
    }

    if (tid < NBIN1) {
        int base  = scan[tid] - tot;        // exclusive prefix = bin start
        offs[tid] = base + part;            // this chunk's write cursor
        if (c == 0) {
            g_start[b * STARTS_PER_B + tid] = base;
            if (tid == 0) g_start[b * STARTS_PER_B + NBIN1] = S_DIM;
        }
    }
    __syncthreads();

    const int* Xb  = X + b * S_DIM + c * CHUNK_S;
    int2*      dst = g_sorted + b * S_DIM;

    #pragma unroll 4
    for (int s = tid; s < CHUNK_S; s += 512) {
        int   bin = sbin[s];
        int   x   = Xb[s];
        float w   = __expf(__ldg(&embedW[x]));
        int   pos = atomicAdd(&offs[bin], 1);
        dst[pos]  = make_int2(x, __float_as_int(w));
    }

    // Peers read our smem hist above; guarantee smem lifetime until all done.
    cluster.sync();
}

// ---------------------------------------------------------------------------
// K2: one warp per (batch, bin). Lane l owns output dims {2l, 2l+1}.
// A single coalesced 256B load fetches 32 (x,w) pairs; __shfl distributes
// them so every gather depends only on a 26-cyc shuffle, not an L2 round
// trip. Padded lanes carry x=0 (zero row) and w=0 -> contribute exactly 0,
// so the inner loop has a FIXED 32-iteration trip count and unrolls fully.
// ---------------------------------------------------------------------------
__global__ __launch_bounds__(256, 8)
void k_bin_reduce(const float* __restrict__ embedX, float* __restrict__ out)
{
    const int warp = (blockIdx.x * blockDim.x + threadIdx.x) >> 5;  // 0..16383
    const int lane = threadIdx.x & 31;
    const int b    = warp >> 8;
    const int bin  = warp & 255;

    const int* gs = g_start + b * STARTS_PER_B;
    const int  s0 = gs[bin];
    const int  s1 = gs[bin + 1];

    const int2*   sxw = g_sorted + b * S_DIM;
    const float2* ex  = reinterpret_cast<const float2*>(embedX);

    float2 acc = make_float2(0.0f, 0.0f);

    for (int base = s0; base < s1; base += 32) {
        int  idx = base + lane;
        int2 xw  = make_int2(0, 0);                 // x=0 (zero row), w=0
        if (idx < s1) xw = __ldg(&sxw[idx]);

        #pragma unroll
        for (int j = 0; j < 32; ++j) {
            int   x = __shfl_sync(0xffffffffu, xw.x, j);
            float w = __int_as_float(__shfl_sync(0xffffffffu, xw.y, j));
            float2 e = __ldg(&ex[x * 32 + lane]);
            acc.x = fmaf(w, e.x, acc.x);
            acc.y = fmaf(w, e.y, acc.y);
        }
    }

    float inv = 1.0f / ((float)(s1 - s0) + 1e-6f);
    reinterpret_cast<float2*>(out)[(b * N_BINS + bin) * 32 + lane] =
        make_float2(acc.x * inv, acc.y * inv);
}

// ---------------------------------------------------------------------------
// Inputs (metadata order):
//   d_in[0] : T        float32 [B, S]
//   d_in[1] : X_ids    int32   [B, S]
//   d_in[2] : embedX_w float32 [N_TOKENS+1, 64]
//   d_in[3] : embedW_w float32 [N_TOKENS+1, 1]
// Output    : float32 [B, 256, 64]
// ---------------------------------------------------------------------------
extern "C" void kernel_launch(void* const* d_in, const int* in_sizes, int n_in,
                              void* d_out, int out_size)
{
    const float* T      = (const float*)d_in[0];
    const int*   X_ids  = (const int*)  d_in[1];
    const float* embedX = (const float*)d_in[2];
    const float* embedW = (const float*)d_in[3];
    float*       out    = (float*)d_out;

    k_sort      <<<B_DIM * NCHUNK, 512>>>(T, X_ids, embedW);
    k_bin_reduce<<<(B_DIM * N_BINS) / 8, 256>>>(embedX, out);
}

// round 8
// speedup vs baseline: 1.0012x; 1.0012x over previous
#include <cuda_runtime.h>
#include <cuda_bf16.h>
#include <cooperative_groups.h>

namespace cg = cooperative_groups;

// Problem constants (pinned by the reference)
#define B_DIM   64
#define S_DIM   8192
#define D_DIM   64
#define N_BINS  256                 // output bins; bin 256 = dummy (T >= 256)
#define NCHUNK  4                   // CTAs (cluster size) per batch in the sort
#define CHUNK_S (S_DIM / NCHUNK)    // 2048 tokens per chunk
#define NBIN1   (N_BINS + 1)        // 257 (incl. dummy)
#define STARTS_PER_B 258

// Scratch (allocation-free rule: __device__ globals)
__device__ int2 g_sorted[B_DIM * S_DIM];          // (x, w-bits), bin-contiguous per batch
__device__ int  g_start [B_DIM * STARTS_PER_B];   // per-batch exclusive bin starts

// ---------------------------------------------------------------------------
// K1: fused per-batch counting sort with SMEM-STAGED (coalesced) output.
// 64 clusters x 4 CTAs, 512 threads/CTA.
//   A: bin each token of the 2048-token chunk -> smem hist + bin cache
//   cluster.sync; read 4 peer hists over DSMEM
//   B: dual Hillis-Steele scan (batch totals + own-chunk hist) gives
//        gbase[bin] (batch-wide start), lbase[bin] (local start),
//        delta[bin] = gbase + part - lbase  (so global addr = p + delta)
//   C: scatter token ids into LOCAL sorted order in smem (smem atomics only)
//   D: copy out in local-position order: global stores are contiguous per
//      bin segment (~2-3 lines per warp vs 32 for direct scatter); the
//      exp(embedW[x]) gather sits in independent iterations and overlaps.
// ---------------------------------------------------------------------------
__global__ __launch_bounds__(512, 2) __cluster_dims__(NCHUNK, 1, 1)
void k_sort(const float* __restrict__ T, const int* __restrict__ X,
            const float* __restrict__ embedW)
{
    __shared__ int            hist [NBIN1];
    __shared__ int            scanT[NBIN1];   // batch-wide totals (scanned)
    __shared__ int            scanL[NBIN1];   // own-chunk hist (scanned)
    __shared__ int            delta[NBIN1];   // p_local + delta[bin] = global pos
    __shared__ int            loffs[NBIN1];   // local scatter cursors
    __shared__ unsigned short sbin [CHUNK_S]; // bin at original position
    __shared__ unsigned short sbin2[CHUNK_S]; // bin at locally-sorted position
    __shared__ int            sx   [CHUNK_S]; // token id at locally-sorted position

    cg::cluster_group cluster = cg::this_cluster();
    const int c   = (int)cluster.block_rank();     // chunk 0..3
    const int b   = blockIdx.x >> 2;               // batch
    const int tid = threadIdx.x;

    for (int i = tid; i < NBIN1; i += 512) hist[i] = 0;
    __syncthreads();

    // --- A: bin + local histogram ---
    const float* Tb = T + b * S_DIM + c * CHUNK_S;
    #pragma unroll 4
    for (int s = tid; s < CHUNK_S; s += 512) {
        float t = Tb[s];
        int bin = (t < 256.0f) ? (int)t : N_BINS;  // t >= 0 -> (int)t == floor
        sbin[s] = (unsigned short)bin;
        atomicAdd(&hist[bin], 1);
    }
    cluster.sync();

    // --- B: peer hist gather + dual scan ---
    int tot = 0, part = 0, own = 0;
    if (tid < NBIN1) {
        #pragma unroll
        for (int cc = 0; cc < NCHUNK; ++cc) {
            const int* rh = cluster.map_shared_rank(hist, cc);
            int h = rh[tid];
            tot += h;
            if (cc < c) part += h;
        }
        own = hist[tid];
        scanT[tid] = tot;
        scanL[tid] = own;
    }
    __syncthreads();

    for (int d = 1; d < NBIN1; d <<= 1) {
        int vT = 0, vL = 0;
        if (tid < NBIN1 && tid >= d) { vT = scanT[tid - d]; vL = scanL[tid - d]; }
        __syncthreads();
        if (tid < NBIN1) { scanT[tid] += vT; scanL[tid] += vL; }
        __syncthreads();
    }

    if (tid < NBIN1) {
        int gbase = scanT[tid] - tot;   // batch-wide bin start
        int lbase = scanL[tid] - own;   // local (chunk) bin start
        loffs[tid] = lbase;
        delta[tid] = gbase + part - lbase;
        if (c == 0) {
            g_start[b * STARTS_PER_B + tid] = gbase;
            if (tid == 0) g_start[b * STARTS_PER_B + NBIN1] = S_DIM;
        }
    }
    __syncthreads();

    // --- C: local scatter into smem (bin-contiguous within chunk) ---
    const int* Xb = X + b * S_DIM + c * CHUNK_S;
    #pragma unroll 4
    for (int s = tid; s < CHUNK_S; s += 512) {
        int bin  = sbin[s];
        int lpos = atomicAdd(&loffs[bin], 1);
        sx[lpos]    = Xb[s];
        sbin2[lpos] = (unsigned short)bin;
    }
    __syncthreads();

    // --- D: coalesced copy-out + weight compute ---
    int2* dst = g_sorted + b * S_DIM;
    #pragma unroll 4
    for (int p = tid; p < CHUNK_S; p += 512) {
        int   x   = sx[p];
        int   bin = sbin2[p];
        float w   = __expf(__ldg(&embedW[x]));
        dst[p + delta[bin]] = make_int2(x, __float_as_int(w));
    }

    cluster.sync();   // peers may still be reading our smem hist
}

// ---------------------------------------------------------------------------
// K2: one warp per (batch, bin); HALF-WARP per token with float4 gathers.
// Lane l: pair = l>>4 (which of 2 concurrent tokens), chunk = l&15 (dims 4c..4c+3).
// Per 32-token block: one coalesced LDG.64 of 32 (x,w) pairs, then 16 fully
// unrolled iterations, each gathering TWO 256B rows via LDG.128 (half the
// load/shuffle instruction count of the float2 version) with ~8 LDG.128 in
// flight (64-reg budget). Halves combine with 4 shfl_xor(16) adds.
// Padded lanes carry x=0 (zero row) and w=0 -> contribute exactly 0.
// ---------------------------------------------------------------------------
__global__ __launch_bounds__(256, 4)
void k_bin_reduce(const float* __restrict__ embedX, float* __restrict__ out)
{
    const int warp = (blockIdx.x * blockDim.x + threadIdx.x) >> 5;  // 0..16383
    const int lane = threadIdx.x & 31;
    const int b    = warp >> 8;
    const int bin  = warp & 255;

    const int pairSel = lane >> 4;    // 0 or 1
    const int chunk   = lane & 15;    // float4 index within the 64-dim row

    const int* gs = g_start + b * STARTS_PER_B;
    const int  s0 = gs[bin];
    const int  s1 = gs[bin + 1];

    const int2*   sxw = g_sorted + b * S_DIM;
    const float4* ex4 = reinterpret_cast<const float4*>(embedX);

    float4 acc = make_float4(0.0f, 0.0f, 0.0f, 0.0f);

    for (int base = s0; base < s1; base += 32) {
        int  idx = base + lane;
        int2 xw  = make_int2(0, 0);                 // x=0 (zero row), w=0
        if (idx < s1) xw = __ldg(&sxw[idx]);

        #pragma unroll
        for (int j = 0; j < 16; ++j) {
            int   src = 2 * j + pairSel;
            int   x = __shfl_sync(0xffffffffu, xw.x, src);
            float w = __int_as_float(__shfl_sync(0xffffffffu, xw.y, src));
            float4 e = __ldg(&ex4[x * 16 + chunk]);
            acc.x = fmaf(w, e.x, acc.x);
            acc.y = fmaf(w, e.y, acc.y);
            acc.z = fmaf(w, e.z, acc.z);
            acc.w = fmaf(w, e.w, acc.w);
        }
    }

    // combine the two half-warp accumulators (tokens were split across halves)
    acc.x += __shfl_xor_sync(0xffffffffu, acc.x, 16);
    acc.y += __shfl_xor_sync(0xffffffffu, acc.y, 16);
    acc.z += __shfl_xor_sync(0xffffffffu, acc.z, 16);
    acc.w += __shfl_xor_sync(0xffffffffu, acc.w, 16);

    if (lane < 16) {
        float inv = 1.0f / ((float)(s1 - s0) + 1e-6f);
        reinterpret_cast<float4*>(out)[(b * N_BINS + bin) * 16 + chunk] =
            make_float4(acc.x * inv, acc.y * inv, acc.z * inv, acc.w * inv);
    }
}

// ---------------------------------------------------------------------------
// Inputs (metadata order):
//   d_in[0] : T        float32 [B, S]
//   d_in[1] : X_ids    int32   [B, S]
//   d_in[2] : embedX_w float32 [N_TOKENS+1, 64]
//   d_in[3] : embedW_w float32 [N_TOKENS+1, 1]
// Output    : float32 [B, 256, 64]
// ---------------------------------------------------------------------------
extern "C" void kernel_launch(void* const* d_in, const int* in_sizes, int n_in,
                              void* d_out, int out_size)
{
    const float* T      = (const float*)d_in[0];
    const int*   X_ids  = (const int*)  d_in[1];
    const float* embedX = (const float*)d_in[2];
    const float* embedW = (const float*)d_in[3];
    float*       out    = (float*)d_out;

    k_sort      <<<B_DIM * NCHUNK, 512>>>(T, X_ids, embedW);
    k_bin_reduce<<<(B_DIM * N_BINS) / 8, 256>>>(embedX, out);
}